// round 12
// baseline (speedup 1.0000x reference)
#include <cuda_runtime.h>

#define ROWS  8192
#define COLS  16384
#define BLOCK 512
#define NWARPS (BLOCK / 32)

// Allocation-free scratch: accumulator + completion counter.
__device__ float    g_acc   = 0.0f;
__device__ unsigned g_count = 0;

// LDG.128 non-coherent, no L1 allocation (zero-reuse stream), L2 256B fetch
// granularity. Single-variable delta vs R11: + L1::no_allocate.
__device__ __forceinline__ float4 ldg128_stream(const float4* __restrict__ a)
{
    float4 v;
    asm volatile("ld.global.nc.L1::no_allocate.L2::256B.v4.f32 "
                 "{%0, %1, %2, %3}, [%4];"
                 : "=f"(v.x), "=f"(v.y), "=f"(v.z), "=f"(v.w)
                 : "l"(a));
    return v;
}

__device__ __forceinline__ void epilogue(float s, float* __restrict__ out,
                                         int nblocks)
{
    // Warp reduce
    #pragma unroll
    for (int o = 16; o > 0; o >>= 1)
        s += __shfl_down_sync(0xffffffffu, s, o);

    __shared__ float ws[NWARPS];
    if ((threadIdx.x & 31) == 0) ws[threadIdx.x >> 5] = s;
    __syncthreads();

    if (threadIdx.x < 32) {
        // Warp-parallel tail: 16 partials reduced by shuffle tree.
        float t = (threadIdx.x < NWARPS) ? ws[threadIdx.x] : 0.0f;
        #pragma unroll
        for (int o = NWARPS / 2; o > 0; o >>= 1)
            t += __shfl_down_sync(0xffffffffu, t, o);

        if (threadIdx.x == 0) {
            float h = fmaxf(t - 1.0f, 0.0f);
            atomicAdd(&g_acc, h);
            // Release-ordered count increment: orders the g_acc add before
            // the counter bump without a full MEMBAR.GPU.
            unsigned done;
            asm volatile("atom.add.release.gpu.u32 %0, [%1], 1;"
                         : "=r"(done) : "l"(&g_count) : "memory");
            if (done == (unsigned)nblocks - 1u) {
                // Acquire-ordered read: all release-ordered g_acc adds visible.
                float total;
                asm volatile("ld.acquire.gpu.f32 %0, [%1];"
                             : "=f"(total) : "l"(&g_acc) : "memory");
                out[0] = total / (float)nblocks;
                // Reset for next graph replay.
                *(volatile float*)&g_acc = 0.0f;
                asm volatile("st.release.gpu.u32 [%0], 0;"
                             :: "l"(&g_count) : "memory");
            }
        }
    }
}

// One CTA per row, 512 threads, 8 fully-unrolled streaming LDG.128 per
// thread (L1 bypass + L2 256B fetch granularity).
__global__ void __launch_bounds__(BLOCK) bloss_unrolled_kernel(
    const float* __restrict__ B, float* __restrict__ out)
{
    const float4* __restrict__ p =
        reinterpret_cast<const float4*>(B + (size_t)blockIdx.x * COLS)
        + threadIdx.x;

    float4 v0 = ldg128_stream(p);
    float4 v1 = ldg128_stream(p + 1 * BLOCK);
    float4 v2 = ldg128_stream(p + 2 * BLOCK);
    float4 v3 = ldg128_stream(p + 3 * BLOCK);
    float4 v4 = ldg128_stream(p + 4 * BLOCK);
    float4 v5 = ldg128_stream(p + 5 * BLOCK);
    float4 v6 = ldg128_stream(p + 6 * BLOCK);
    float4 v7 = ldg128_stream(p + 7 * BLOCK);

    float s0 = (v0.x + v0.y) + (v0.z + v0.w);
    float s1 = (v1.x + v1.y) + (v1.z + v1.w);
    float s2 = (v2.x + v2.y) + (v2.z + v2.w);
    float s3 = (v3.x + v3.y) + (v3.z + v3.w);
    float s4 = (v4.x + v4.y) + (v4.z + v4.w);
    float s5 = (v5.x + v5.y) + (v5.z + v5.w);
    float s6 = (v6.x + v6.y) + (v6.z + v6.w);
    float s7 = (v7.x + v7.y) + (v7.z + v7.w);

    float s = ((s0 + s1) + (s2 + s3)) + ((s4 + s5) + (s6 + s7));
    epilogue(s, out, ROWS);
}

// Generic fallback (any cols divisible by 4): one row per CTA, LDG.128 loop.
__global__ void __launch_bounds__(BLOCK) bloss_generic_kernel(
    const float* __restrict__ B, float* __restrict__ out, int cols)
{
    const float4* __restrict__ p =
        reinterpret_cast<const float4*>(B + (size_t)blockIdx.x * (size_t)cols);
    const int n4 = cols >> 2;

    float s0 = 0.0f, s1 = 0.0f, s2 = 0.0f, s3 = 0.0f;
    int i = threadIdx.x;
    for (; i + 3 * BLOCK < n4; i += 4 * BLOCK) {
        float4 v0 = p[i];
        float4 v1 = p[i + BLOCK];
        float4 v2 = p[i + 2 * BLOCK];
        float4 v3 = p[i + 3 * BLOCK];
        s0 += (v0.x + v0.y) + (v0.z + v0.w);
        s1 += (v1.x + v1.y) + (v1.z + v1.w);
        s2 += (v2.x + v2.y) + (v2.z + v2.w);
        s3 += (v3.x + v3.y) + (v3.z + v3.w);
    }
    for (; i < n4; i += BLOCK) {
        float4 v = p[i];
        s0 += (v.x + v.y) + (v.z + v.w);
    }
    epilogue((s0 + s1) + (s2 + s3), out, ROWS);
}

extern "C" void kernel_launch(void* const* d_in, const int* in_sizes, int n_in,
                              void* d_out, int out_size)
{
    const float* B = (const float*)d_in[0];
    const int rows = ROWS;                   // 8192 per problem spec
    const int cols = in_sizes[0] / rows;     // 16384

    if (cols == COLS)
        bloss_unrolled_kernel<<<rows, BLOCK>>>(B, (float*)d_out);
    else
        bloss_generic_kernel<<<rows, BLOCK>>>(B, (float*)d_out, cols);
}